// round 9
// baseline (speedup 1.0000x reference)
#include <cuda_runtime.h>
#include <cstdint>

// Problem constants: B=2, H=32, D=128, S_MAX=8192, S_NEW=512 (fp32).
#define BH 64
#define DHEAD 128
#define SMAX_MAX 8192

// Inverse scatter map: g_inv[s] = i+1 if input_pos[i] == s else 0.
// Zero-initialized at module load; scatter_inv rewrites the same entries
// identically on every replay, so no reset kernel is needed.
__device__ int g_inv[SMAX_MAX];

__global__ void scatter_inv_kernel(const int* __restrict__ pos, int snew) {
    int i = blockIdx.x * blockDim.x + threadIdx.x;
    if (i < snew) {
        int p = pos[i];
        if (p >= 0 && p < SMAX_MAX) g_inv[p] = i + 1;
    }
#if __CUDA_ARCH__ >= 900
    cudaTriggerProgrammaticLaunchCompletion();
#endif
}

// One fused launch, 512 threads/block, transpose : copy blocks interleaved 1:4
// (bid % 5 == 0 -> transpose). For smax % 64 == 0:
//   transBlocks = BH*smax/64, copyBlocks = BH*smax*32/512 = 4*transBlocks.
//
// Transpose path: 64 s x 128 d tile (each d-row read is 256 B contiguous),
// float4 on both global sides, shared tile [s][d] pitch 132 (rows 16B-aligned
// for LDS.128), fused scatter epilogue. Fully-covered tiles skip the kt load.
// Copy path: one float4 per thread per output; each D=128 row = 32 float4 so
// every warp owns one (bh,s) row -> scatter branch warp-uniform.
__global__ void __launch_bounds__(512)
fused_main_kernel(const float4* __restrict__ kt,      // [BH, D, S_MAX/4]
                  const float4* __restrict__ k_cache, // [BH, S_MAX, 32]
                  const float4* __restrict__ v_cache,
                  const float4* __restrict__ k_val,   // [BH, S_NEW, 32]
                  const float4* __restrict__ v_val,
                  float4* __restrict__ out0,
                  float4* __restrict__ out1,
                  float4* __restrict__ out2,
                  int smax, int snew) {
    __shared__ float tile[64][132];   // 132*4 = 528B pitch (16B aligned)
    __shared__ int covFlags[2];
    const int t   = threadIdx.x;      // 0..511
    const int bid = blockIdx.x;
    const int q   = bid / 5;

#if __CUDA_ARCH__ >= 900
    cudaGridDependencySynchronize();
#endif

    if (bid - q * 5 == 0) {
        // ============ transpose path: 64 s-values starting at s0 ============
        const int nSblk = smax >> 6;
        const int bh = q / nSblk;
        const int s0 = (q % nSblk) * 64;

        // Coverage: skip the kt load if all 64 rows are scattered.
        if (t < 64) {
            int c = (g_inv[s0 + t] > 0);
            int all = __all_sync(0xffffffffu, c);
            if ((t & 31) == 0) covFlags[t >> 5] = all;
        }
        __syncthreads();

        if (!(covFlags[0] & covFlags[1])) {
            // ---- load: float4 along s (16 float4 span 64 s-values) ----
            const int s4   = t & 15;
            const int d_lo = t >> 4;          // 0..31
            const size_t srow4 = (size_t)smax >> 2;
            const float4* src = kt + (size_t)bh * DHEAD * srow4;

            #pragma unroll
            for (int it = 0; it < 4; ++it) {
                int d = d_lo + it * 32;
                float4 v = src[(size_t)d * srow4 + (size_t)(s0 >> 2) + s4];
                tile[s4 * 4 + 0][d] = v.x;
                tile[s4 * 4 + 1][d] = v.y;
                tile[s4 * 4 + 2][d] = v.z;
                tile[s4 * 4 + 3][d] = v.w;
            }
            __syncthreads();
        }

        // ---- store: float4 along d, one warp per output row ----
        const int l = t & 31;             // float4 column 0..31
        const int w = t >> 5;             // warp 0..15
        float4* dst = out0 + (size_t)bh * smax * 32;
        const float4* kv = k_val + (size_t)bh * snew * 32;

        #pragma unroll
        for (int it = 0; it < 4; ++it) {
            int s  = w + it * 16;         // 0..63
            int gs = s0 + s;
            int i  = g_inv[gs];           // warp-uniform
            float4 v;
            if (i > 0) v = kv[(size_t)(i - 1) * 32 + l];
            else       v = *(const float4*)&tile[s][l * 4];
            dst[(size_t)gs * 32 + l] = v;
        }
    } else {
        // ================= k/v copy path =================
        size_t cb  = (size_t)(bid - q - 1);   // copy block index (slots removed)
        size_t idx = cb * 512 + t;
        size_t total = (size_t)BH * smax * 32;
        if (idx >= total) return;

        int j = (int)(idx & 31);
        size_t row = idx >> 5;                // (bh, s)
        int s = (int)(row % smax);
        size_t bh = row / smax;

        int i = g_inv[s];
        if (i > 0) {
            size_t src = ((bh * (size_t)snew) + (size_t)(i - 1)) * 32 + j;
            out1[idx] = k_val[src];
            out2[idx] = v_val[src];
        } else {
            out1[idx] = k_cache[idx];
            out2[idx] = v_cache[idx];
        }
    }
}

extern "C" void kernel_launch(void* const* d_in, const int* in_sizes, int n_in,
                              void* d_out, int out_size) {
    const int*   pos      = (const int*)d_in[0];
    const float* k_val    = (const float*)d_in[1];
    const float* v_val    = (const float*)d_in[2];
    const float* k_cache  = (const float*)d_in[3];
    const float* kt_cache = (const float*)d_in[4];
    const float* v_cache  = (const float*)d_in[5];

    int snew = in_sizes[0];
    int smax = in_sizes[3] / (BH * DHEAD);

    float* out  = (float*)d_out;
    size_t per  = (size_t)BH * smax * DHEAD;
    float* out0 = out;             // ktᵀ result
    float* out1 = out + per;       // k result
    float* out2 = out + 2 * per;   // v result

    // 1. Build inverse scatter map (no reset: 0 = invalid encoding).
    scatter_inv_kernel<<<(snew + 511) / 512, 512>>>(pos, snew);

    // 2. Fused launch with PDL: overlaps its launch with scatter_inv's tail.
    int transBlocks = (smax / 64) * BH;           // 8192
    int totalBlocks = transBlocks * 5;            // transpose + 4x copy
    {
        cudaLaunchConfig_t cfg = {};
        cfg.gridDim  = dim3((unsigned)totalBlocks);
        cfg.blockDim = dim3(512);
        cfg.dynamicSmemBytes = 0;
        cudaLaunchAttribute attrs[1];
        attrs[0].id = cudaLaunchAttributeProgrammaticStreamSerialization;
        attrs[0].val.programmaticStreamSerializationAllowed = 1;
        cfg.attrs = attrs;
        cfg.numAttrs = 1;
        cudaLaunchKernelEx(&cfg, fused_main_kernel,
                           (const float4*)kt_cache,
                           (const float4*)k_cache, (const float4*)v_cache,
                           (const float4*)k_val,   (const float4*)v_val,
                           (float4*)out0, (float4*)out1, (float4*)out2,
                           smax, snew);
    }
}

// round 10
// speedup vs baseline: 1.0105x; 1.0105x over previous
#include <cuda_runtime.h>
#include <cstdint>

// Problem constants: B=2, H=32, D=128, S_MAX=8192, S_NEW=512 (fp32).
#define BH 64
#define DHEAD 128
#define SMAX_MAX 8192

// Inverse scatter map: g_inv[s] = i+1 if input_pos[i] == s else 0.
// Zero-initialized at module load; scatter_inv rewrites the same entries
// identically on every replay, so no reset kernel is needed.
__device__ int g_inv[SMAX_MAX];

__global__ void scatter_inv_kernel(const int* __restrict__ pos, int snew) {
    int i = blockIdx.x * blockDim.x + threadIdx.x;
    if (i < snew) {
        int p = pos[i];
        if (p >= 0 && p < SMAX_MAX) g_inv[p] = i + 1;
    }
#if __CUDA_ARCH__ >= 900
    cudaTriggerProgrammaticLaunchCompletion();
#endif
}

// One fused launch, 256 threads/block, transpose : copy blocks interleaved 1:4
// (bid % 5 == 0 -> transpose; copyBlocks == 4 * transBlocks for smax % 32 == 0).
// Compile-time specialized on (SMAX, SNEW) so all div/mod are shifts/masks;
// memory access pattern identical to the proven R8 kernel.
//
// Transpose path: 32 s x 128 d tile, float4 on both global sides, shared tile
// [s][d] pitch 132 (rows 16B-aligned for LDS.128), fused scatter epilogue.
// Fully-covered tiles skip the kt load.
// Copy path: one float4 per thread per output; each D=128 row = 32 float4 so
// every warp owns one (bh,s) row -> scatter branch warp-uniform.
template <int SMAX, int SNEW>
__global__ void __launch_bounds__(256)
fused_main_kernel(const float4* __restrict__ kt,      // [BH, D, SMAX/4]
                  const float4* __restrict__ k_cache, // [BH, SMAX, 32]
                  const float4* __restrict__ v_cache,
                  const float4* __restrict__ k_val,   // [BH, SNEW, 32]
                  const float4* __restrict__ v_val,
                  float4* __restrict__ out0,
                  float4* __restrict__ out1,
                  float4* __restrict__ out2) {
    __shared__ float tile[32][132];   // 132*4 = 528B pitch (16B aligned)
    const int t   = threadIdx.x;      // 0..255
    const int bid = blockIdx.x;
    const int q   = bid / 5;

#if __CUDA_ARCH__ >= 900
    cudaGridDependencySynchronize();
#endif

    if (bid - q * 5 == 0) {
        // ================= transpose path (tile index q) =================
        constexpr int nSblk = SMAX >> 5;      // compile-time
        const int bh = q / nSblk;             // -> shift
        const int s0 = (q % nSblk) * 32;      // -> mask+shift

        // Skip the kt load if every row of this tile is scattered.
        int covered = 1;
        if (t < 32) covered = (g_inv[s0 + t] > 0);
        if (!__syncthreads_and(covered)) {
            // ---- load: float4 along s ----
            const int s4   = t & 7;           // 8 float4 span 32 s
            const int d_lo = t >> 3;          // 0..31
            constexpr int SROW4 = SMAX >> 2;
            const float4* src = kt + (size_t)bh * (DHEAD * SROW4);

            #pragma unroll
            for (int it = 0; it < 4; ++it) {
                int d = d_lo + it * 32;
                float4 v = src[d * SROW4 + (s0 >> 2) + s4];
                tile[s4 * 4 + 0][d] = v.x;
                tile[s4 * 4 + 1][d] = v.y;
                tile[s4 * 4 + 2][d] = v.z;
                tile[s4 * 4 + 3][d] = v.w;
            }
            __syncthreads();
        }

        // ---- store: float4 along d, one warp per output row ----
        const int l = t & 31;
        const int w = t >> 5;
        float4* dst = out0 + (size_t)bh * (SMAX * 32);
        const float4* kv = k_val + (size_t)bh * (SNEW * 32);

        #pragma unroll
        for (int it = 0; it < 4; ++it) {
            int s  = w + it * 8;
            int gs = s0 + s;
            int i  = g_inv[gs];               // warp-uniform
            float4 v;
            if (i > 0) v = kv[(i - 1) * 32 + l];
            else       v = *(const float4*)&tile[s][l * 4];
            dst[(size_t)gs * 32 + l] = v;
        }
    } else {
        // ================= k/v copy path =================
        size_t cb  = (size_t)(bid - q - 1);   // copy block index (slots removed)
        size_t idx = cb * 256 + t;

        int j = (int)(idx & 31);
        size_t row = idx >> 5;                // (bh, s)
        int s = (int)(row & (SMAX - 1));      // mask (power of two)
        size_t bh = row >> (SMAX == 8192 ? 13 : 0);  // shift for SMAX=8192
        if (SMAX != 8192) bh = row / SMAX;    // dead when specialized

        int i = g_inv[s];
        if (i > 0) {
            size_t src = (bh * SNEW + (size_t)(i - 1)) * 32 + j;
            out1[idx] = k_val[src];
            out2[idx] = v_val[src];
        } else {
            out1[idx] = k_cache[idx];
            out2[idx] = v_cache[idx];
        }
    }
}

// Generic fallback (runtime sizes), same structure as R8.
__global__ void __launch_bounds__(256)
fused_main_generic(const float4* __restrict__ kt,
                   const float4* __restrict__ k_cache,
                   const float4* __restrict__ v_cache,
                   const float4* __restrict__ k_val,
                   const float4* __restrict__ v_val,
                   float4* __restrict__ out0,
                   float4* __restrict__ out1,
                   float4* __restrict__ out2,
                   int smax, int snew) {
    __shared__ float tile[32][132];
    const int t   = threadIdx.x;
    const int bid = blockIdx.x;
    const int q   = bid / 5;

#if __CUDA_ARCH__ >= 900
    cudaGridDependencySynchronize();
#endif

    if (bid - q * 5 == 0) {
        const int nSblk = smax >> 5;
        const int bh = q / nSblk;
        const int s0 = (q % nSblk) * 32;

        int covered = 1;
        if (t < 32) covered = (g_inv[s0 + t] > 0);
        if (!__syncthreads_and(covered)) {
            const int s4   = t & 7;
            const int d_lo = t >> 3;
            const size_t srow4 = (size_t)smax >> 2;
            const float4* src = kt + (size_t)bh * DHEAD * srow4;
            #pragma unroll
            for (int it = 0; it < 4; ++it) {
                int d = d_lo + it * 32;
                float4 v = src[(size_t)d * srow4 + (size_t)(s0 >> 2) + s4];
                tile[s4 * 4 + 0][d] = v.x;
                tile[s4 * 4 + 1][d] = v.y;
                tile[s4 * 4 + 2][d] = v.z;
                tile[s4 * 4 + 3][d] = v.w;
            }
            __syncthreads();
        }

        const int l = t & 31;
        const int w = t >> 5;
        float4* dst = out0 + (size_t)bh * smax * 32;
        #pragma unroll
        for (int it = 0; it < 4; ++it) {
            int s  = w + it * 8;
            int gs = s0 + s;
            int i  = g_inv[gs];
            float4 v;
            if (i > 0) v = k_val[((size_t)bh * snew + (size_t)(i - 1)) * 32 + l];
            else       v = *(const float4*)&tile[s][l * 4];
            dst[(size_t)gs * 32 + l] = v;
        }
    } else {
        size_t cb  = (size_t)(bid - q - 1);
        size_t idx = cb * 256 + t;
        size_t total = (size_t)BH * smax * 32;
        if (idx >= total) return;

        int j = (int)(idx & 31);
        size_t row = idx >> 5;
        int s = (int)(row % smax);
        size_t bh = row / smax;

        int i = g_inv[s];
        if (i > 0) {
            size_t src = ((bh * (size_t)snew) + (size_t)(i - 1)) * 32 + j;
            out1[idx] = k_val[src];
            out2[idx] = v_val[src];
        } else {
            out1[idx] = k_cache[idx];
            out2[idx] = v_cache[idx];
        }
    }
}

extern "C" void kernel_launch(void* const* d_in, const int* in_sizes, int n_in,
                              void* d_out, int out_size) {
    const int*   pos      = (const int*)d_in[0];
    const float* k_val    = (const float*)d_in[1];
    const float* v_val    = (const float*)d_in[2];
    const float* k_cache  = (const float*)d_in[3];
    const float* kt_cache = (const float*)d_in[4];
    const float* v_cache  = (const float*)d_in[5];

    int snew = in_sizes[0];
    int smax = in_sizes[3] / (BH * DHEAD);

    float* out  = (float*)d_out;
    size_t per  = (size_t)BH * smax * DHEAD;
    float* out0 = out;             // ktᵀ result
    float* out1 = out + per;       // k result
    float* out2 = out + 2 * per;   // v result

    // 1. Build inverse scatter map (no reset: 0 = invalid encoding).
    scatter_inv_kernel<<<(snew + 511) / 512, 512>>>(pos, snew);

    // 2. Fused launch with PDL, specialized for the benchmark shape.
    int transBlocks = (smax / 32) * BH;
    int totalBlocks = transBlocks * 5;

    cudaLaunchConfig_t cfg = {};
    cfg.gridDim  = dim3((unsigned)totalBlocks);
    cfg.blockDim = dim3(256);
    cfg.dynamicSmemBytes = 0;
    cudaLaunchAttribute attrs[1];
    attrs[0].id = cudaLaunchAttributeProgrammaticStreamSerialization;
    attrs[0].val.programmaticStreamSerializationAllowed = 1;
    cfg.attrs = attrs;
    cfg.numAttrs = 1;

    if (smax == 8192 && snew == 512) {
        cudaLaunchKernelEx(&cfg, fused_main_kernel<8192, 512>,
                           (const float4*)kt_cache,
                           (const float4*)k_cache, (const float4*)v_cache,
                           (const float4*)k_val,   (const float4*)v_val,
                           (float4*)out0, (float4*)out1, (float4*)out2);
    } else {
        cudaLaunchKernelEx(&cfg, fused_main_generic,
                           (const float4*)kt_cache,
                           (const float4*)k_cache, (const float4*)v_cache,
                           (const float4*)k_val,   (const float4*)v_val,
                           (float4*)out0, (float4*)out1, (float4*)out2,
                           smax, snew);
    }
}

// round 11
// speedup vs baseline: 1.0177x; 1.0070x over previous
#include <cuda_runtime.h>
#include <cstdint>

// Problem constants: B=2, H=32, D=128, S_MAX=8192, S_NEW=512 (fp32).
#define BH 64
#define DHEAD 128

// ============================================================================
// Specialized single-kernel path (SMAX, SNEW compile-time; powers of two).
//
// One launch, 256 threads/block, transpose : copy blocks interleaved 1:4
// (bid % 5 == 0 -> transpose; copyBlocks == 4 * transBlocks).
//
// Each block builds a LOCAL inverse-scatter map in shared memory for just the
// s-rows it owns (8 rows for copy blocks, 32 for transpose blocks) by
// scanning pos[0..SNEW) — 2 coalesced loads/thread, L2-broadcast. This
// removes the separate scatter kernel, the PDL handshake, and the global map.
//
// Transpose path: 32 s x 128 d tile, float4 on both global sides, shared tile
// [s][d] pitch 132 (rows 16B-aligned for LDS.128), fused scatter epilogue.
// Fully-covered tiles skip the kt load.
// Copy path: one float4 per thread per output; each D=128 row = 32 float4 so
// every warp owns one (bh,s) row -> scatter branch warp-uniform (map[w]).
// ============================================================================
template <int SMAX, int SNEW>
__global__ void __launch_bounds__(256)
fused_all_kernel(const int*    __restrict__ pos,     // [SNEW]
                 const float4* __restrict__ kt,      // [BH, D, SMAX/4]
                 const float4* __restrict__ k_cache, // [BH, SMAX, 32]
                 const float4* __restrict__ v_cache,
                 const float4* __restrict__ k_val,   // [BH, SNEW, 32]
                 const float4* __restrict__ v_val,
                 float4* __restrict__ out0,
                 float4* __restrict__ out1,
                 float4* __restrict__ out2) {
    __shared__ float tile[32][132];   // 132*4 = 528B pitch (16B aligned)
    __shared__ int   map[32];         // local inverse map: s-local -> i+1 (0 = none)

    const int t   = threadIdx.x;      // 0..255
    const int bid = blockIdx.x;
    const int q   = bid / 5;
    const bool isTrans = (bid - q * 5 == 0);

    constexpr int nSblk   = SMAX >> 5;      // 32-s tiles per bh
    constexpr int BH_SHIFT = (SMAX == 8192) ? 13 : 0;  // log2(SMAX) when specialized

    // ---- figure out which s-rows this block owns ----
    int bh, s_lo, nrows;
    size_t cb = 0;
    if (isTrans) {
        bh    = q / nSblk;
        s_lo  = (q % nSblk) * 32;
        nrows = 32;
    } else {
        cb = (size_t)(bid - q - 1);         // copy block index (slots removed)
        size_t row0 = (cb * 256) >> 5;      // first (bh,s) row; 256 f4 = 8 rows
        bh    = (int)(row0 >> BH_SHIFT);
        s_lo  = (int)(row0 & (SMAX - 1));
        nrows = 8;
    }

    // ---- build the local inverse map ----
    if (t < 32) map[t] = 0;
    __syncthreads();
    #pragma unroll
    for (int i = t; i < SNEW; i += 256) {
        int p = pos[i] - s_lo;
        if ((unsigned)p < (unsigned)nrows) map[p] = i + 1;
    }
    __syncthreads();

    if (isTrans) {
        // ================= transpose path =================
        // Skip the kt load if every row of this tile is scattered.
        int covered = 1;
        if (t < 32) covered = (map[t] > 0);
        if (!__syncthreads_and(covered)) {
            // ---- load: float4 along s ----
            const int s4   = t & 7;           // 8 float4 span 32 s
            const int d_lo = t >> 3;          // 0..31
            constexpr int SROW4 = SMAX >> 2;
            const float4* src = kt + (size_t)bh * (DHEAD * SROW4);

            #pragma unroll
            for (int it = 0; it < 4; ++it) {
                int d = d_lo + it * 32;
                float4 v = src[d * SROW4 + (s_lo >> 2) + s4];
                tile[s4 * 4 + 0][d] = v.x;
                tile[s4 * 4 + 1][d] = v.y;
                tile[s4 * 4 + 2][d] = v.z;
                tile[s4 * 4 + 3][d] = v.w;
            }
            __syncthreads();
        }

        // ---- store: float4 along d, one warp per output row ----
        const int l = t & 31;
        const int w = t >> 5;
        float4* dst = out0 + (size_t)bh * (SMAX * 32);
        const float4* kv = k_val + (size_t)bh * (SNEW * 32);

        #pragma unroll
        for (int it = 0; it < 4; ++it) {
            int s  = w + it * 8;
            int i  = map[s];                  // warp-uniform
            float4 v;
            if (i > 0) v = kv[(i - 1) * 32 + l];
            else       v = *(const float4*)&tile[s][l * 4];
            dst[(size_t)(s_lo + s) * 32 + l] = v;
        }
    } else {
        // ================= k/v copy path =================
        size_t idx = cb * 256 + t;            // global float4 index
        int j = t & 31;                       // float4 column within row
        int w = t >> 5;                       // local row 0..7

        int i = map[w];                       // warp-uniform
        if (i > 0) {
            size_t src = ((size_t)bh * SNEW + (size_t)(i - 1)) * 32 + j;
            out1[idx] = k_val[src];
            out2[idx] = v_val[src];
        } else {
            out1[idx] = k_cache[idx];
            out2[idx] = v_cache[idx];
        }
    }
}

// ============================================================================
// Generic fallback (runtime sizes): two launches, global inverse map.
// ============================================================================
#define SMAX_MAX 8192
__device__ int g_inv[SMAX_MAX];

__global__ void scatter_inv_kernel(const int* __restrict__ pos, int snew) {
    int i = blockIdx.x * blockDim.x + threadIdx.x;
    if (i < snew) {
        int p = pos[i];
        if (p >= 0 && p < SMAX_MAX) g_inv[p] = i + 1;
    }
}

__global__ void __launch_bounds__(256)
fused_main_generic(const float4* __restrict__ kt,
                   const float4* __restrict__ k_cache,
                   const float4* __restrict__ v_cache,
                   const float4* __restrict__ k_val,
                   const float4* __restrict__ v_val,
                   float4* __restrict__ out0,
                   float4* __restrict__ out1,
                   float4* __restrict__ out2,
                   int smax, int snew) {
    __shared__ float tile[32][132];
    const int t   = threadIdx.x;
    const int bid = blockIdx.x;
    const int q   = bid / 5;

    if (bid - q * 5 == 0) {
        const int nSblk = smax >> 5;
        const int bh = q / nSblk;
        const int s0 = (q % nSblk) * 32;

        int covered = 1;
        if (t < 32) covered = (g_inv[s0 + t] > 0);
        if (!__syncthreads_and(covered)) {
            const int s4   = t & 7;
            const int d_lo = t >> 3;
            const size_t srow4 = (size_t)smax >> 2;
            const float4* src = kt + (size_t)bh * DHEAD * srow4;
            #pragma unroll
            for (int it = 0; it < 4; ++it) {
                int d = d_lo + it * 32;
                float4 v = src[(size_t)d * srow4 + (size_t)(s0 >> 2) + s4];
                tile[s4 * 4 + 0][d] = v.x;
                tile[s4 * 4 + 1][d] = v.y;
                tile[s4 * 4 + 2][d] = v.z;
                tile[s4 * 4 + 3][d] = v.w;
            }
            __syncthreads();
        }

        const int l = t & 31;
        const int w = t >> 5;
        float4* dst = out0 + (size_t)bh * smax * 32;
        #pragma unroll
        for (int it = 0; it < 4; ++it) {
            int s  = w + it * 8;
            int gs = s0 + s;
            int i  = g_inv[gs];
            float4 v;
            if (i > 0) v = k_val[((size_t)bh * snew + (size_t)(i - 1)) * 32 + l];
            else       v = *(const float4*)&tile[s][l * 4];
            dst[(size_t)gs * 32 + l] = v;
        }
    } else {
        size_t cb  = (size_t)(bid - q - 1);
        size_t idx = cb * 256 + t;
        size_t total = (size_t)BH * smax * 32;
        if (idx >= total) return;

        int j = (int)(idx & 31);
        size_t row = idx >> 5;
        int s = (int)(row % smax);
        size_t bh = row / smax;

        int i = g_inv[s];
        if (i > 0) {
            size_t src = ((bh * (size_t)snew) + (size_t)(i - 1)) * 32 + j;
            out1[idx] = k_val[src];
            out2[idx] = v_val[src];
        } else {
            out1[idx] = k_cache[idx];
            out2[idx] = v_cache[idx];
        }
    }
}

extern "C" void kernel_launch(void* const* d_in, const int* in_sizes, int n_in,
                              void* d_out, int out_size) {
    const int*   pos      = (const int*)d_in[0];
    const float* k_val    = (const float*)d_in[1];
    const float* v_val    = (const float*)d_in[2];
    const float* k_cache  = (const float*)d_in[3];
    const float* kt_cache = (const float*)d_in[4];
    const float* v_cache  = (const float*)d_in[5];

    int snew = in_sizes[0];
    int smax = in_sizes[3] / (BH * DHEAD);

    float* out  = (float*)d_out;
    size_t per  = (size_t)BH * smax * DHEAD;
    float* out0 = out;             // ktᵀ result
    float* out1 = out + per;       // k result
    float* out2 = out + 2 * per;   // v result

    int transBlocks = (smax / 32) * BH;           // 16384 for smax=8192
    int totalBlocks = transBlocks * 5;            // transpose + 4x copy

    if (smax == 8192 && snew == 512) {
        // Single launch: per-block local inverse maps, no dependency chain.
        fused_all_kernel<8192, 512><<<totalBlocks, 256>>>(
            pos,
            (const float4*)kt_cache,
            (const float4*)k_cache, (const float4*)v_cache,
            (const float4*)k_val,   (const float4*)v_val,
            (float4*)out0, (float4*)out1, (float4*)out2);
    } else {
        scatter_inv_kernel<<<(snew + 511) / 512, 512>>>(pos, snew);
        fused_main_generic<<<totalBlocks, 256>>>(
            (const float4*)kt_cache,
            (const float4*)k_cache, (const float4*)v_cache,
            (const float4*)k_val,   (const float4*)v_val,
            (float4*)out0, (float4*)out1, (float4*)out2,
            smax, snew);
    }
}

// round 12
// speedup vs baseline: 1.0178x; 1.0001x over previous
#include <cuda_runtime.h>
#include <cstdint>

// Problem constants: B=2, H=32, D=128, S_MAX=8192, S_NEW=512 (fp32).
#define BH 64
#define DHEAD 128

// ============================================================================
// Specialized single-kernel path (SMAX, SNEW compile-time; powers of two).
//
// One launch, 256 threads/block, transpose : copy blocks interleaved 1:4
// (bid % 5 == 0 -> transpose; copyBlocks == 4 * transBlocks).
//
// Each block builds a LOCAL inverse-scatter map in shared memory for just the
// s-rows it owns (8 rows for copy blocks, 32 for transpose blocks) by
// scanning pos[0..SNEW) — 2 coalesced loads/thread, L2-broadcast.
//
// R12 change (single variable vs R11): output stores use __stcs (evict-first)
// — the 805 MB write stream has zero reuse and should not allocate in L2.
// All loads keep default caching (k_val/v_val have 3x reuse).
// ============================================================================
template <int SMAX, int SNEW>
__global__ void __launch_bounds__(256)
fused_all_kernel(const int*    __restrict__ pos,     // [SNEW]
                 const float4* __restrict__ kt,      // [BH, D, SMAX/4]
                 const float4* __restrict__ k_cache, // [BH, SMAX, 32]
                 const float4* __restrict__ v_cache,
                 const float4* __restrict__ k_val,   // [BH, SNEW, 32]
                 const float4* __restrict__ v_val,
                 float4* __restrict__ out0,
                 float4* __restrict__ out1,
                 float4* __restrict__ out2) {
    __shared__ float tile[32][132];   // 132*4 = 528B pitch (16B aligned)
    __shared__ int   map[32];         // local inverse map: s-local -> i+1 (0 = none)

    const int t   = threadIdx.x;      // 0..255
    const int bid = blockIdx.x;
    const int q   = bid / 5;
    const bool isTrans = (bid - q * 5 == 0);

    constexpr int nSblk    = SMAX >> 5;                 // 32-s tiles per bh
    constexpr int BH_SHIFT = (SMAX == 8192) ? 13 : 0;   // log2(SMAX) when specialized

    // ---- figure out which s-rows this block owns ----
    int bh, s_lo, nrows;
    size_t cb = 0;
    if (isTrans) {
        bh    = q / nSblk;
        s_lo  = (q % nSblk) * 32;
        nrows = 32;
    } else {
        cb = (size_t)(bid - q - 1);         // copy block index (slots removed)
        size_t row0 = (cb * 256) >> 5;      // first (bh,s) row; 256 f4 = 8 rows
        bh    = (int)(row0 >> BH_SHIFT);
        s_lo  = (int)(row0 & (SMAX - 1));
        nrows = 8;
    }

    // ---- build the local inverse map ----
    if (t < 32) map[t] = 0;
    __syncthreads();
    #pragma unroll
    for (int i = t; i < SNEW; i += 256) {
        int p = pos[i] - s_lo;
        if ((unsigned)p < (unsigned)nrows) map[p] = i + 1;
    }
    __syncthreads();

    if (isTrans) {
        // ================= transpose path =================
        // Skip the kt load if every row of this tile is scattered.
        int covered = 1;
        if (t < 32) covered = (map[t] > 0);
        if (!__syncthreads_and(covered)) {
            // ---- load: float4 along s ----
            const int s4   = t & 7;           // 8 float4 span 32 s
            const int d_lo = t >> 3;          // 0..31
            constexpr int SROW4 = SMAX >> 2;
            const float4* src = kt + (size_t)bh * (DHEAD * SROW4);

            #pragma unroll
            for (int it = 0; it < 4; ++it) {
                int d = d_lo + it * 32;
                float4 v = src[d * SROW4 + (s_lo >> 2) + s4];
                tile[s4 * 4 + 0][d] = v.x;
                tile[s4 * 4 + 1][d] = v.y;
                tile[s4 * 4 + 2][d] = v.z;
                tile[s4 * 4 + 3][d] = v.w;
            }
            __syncthreads();
        }

        // ---- store: float4 along d, one warp per output row ----
        const int l = t & 31;
        const int w = t >> 5;
        float4* dst = out0 + (size_t)bh * (SMAX * 32);
        const float4* kv = k_val + (size_t)bh * (SNEW * 32);

        #pragma unroll
        for (int it = 0; it < 4; ++it) {
            int s  = w + it * 8;
            int i  = map[s];                  // warp-uniform
            float4 v;
            if (i > 0) v = kv[(i - 1) * 32 + l];
            else       v = *(const float4*)&tile[s][l * 4];
            __stcs(&dst[(size_t)(s_lo + s) * 32 + l], v);
        }
    } else {
        // ================= k/v copy path =================
        size_t idx = cb * 256 + t;            // global float4 index
        int j = t & 31;                       // float4 column within row
        int w = t >> 5;                       // local row 0..7

        int i = map[w];                       // warp-uniform
        float4 a, b;
        if (i > 0) {
            size_t src = ((size_t)bh * SNEW + (size_t)(i - 1)) * 32 + j;
            a = k_val[src];
            b = v_val[src];
        } else {
            a = k_cache[idx];
            b = v_cache[idx];
        }
        __stcs(&out1[idx], a);
        __stcs(&out2[idx], b);
    }
}

// ============================================================================
// Generic fallback (runtime sizes): two launches, global inverse map.
// ============================================================================
#define SMAX_MAX 8192
__device__ int g_inv[SMAX_MAX];

__global__ void scatter_inv_kernel(const int* __restrict__ pos, int snew) {
    int i = blockIdx.x * blockDim.x + threadIdx.x;
    if (i < snew) {
        int p = pos[i];
        if (p >= 0 && p < SMAX_MAX) g_inv[p] = i + 1;
    }
}

__global__ void __launch_bounds__(256)
fused_main_generic(const float4* __restrict__ kt,
                   const float4* __restrict__ k_cache,
                   const float4* __restrict__ v_cache,
                   const float4* __restrict__ k_val,
                   const float4* __restrict__ v_val,
                   float4* __restrict__ out0,
                   float4* __restrict__ out1,
                   float4* __restrict__ out2,
                   int smax, int snew) {
    __shared__ float tile[32][132];
    const int t   = threadIdx.x;
    const int bid = blockIdx.x;
    const int q   = bid / 5;

    if (bid - q * 5 == 0) {
        const int nSblk = smax >> 5;
        const int bh = q / nSblk;
        const int s0 = (q % nSblk) * 32;

        int covered = 1;
        if (t < 32) covered = (g_inv[s0 + t] > 0);
        if (!__syncthreads_and(covered)) {
            const int s4   = t & 7;
            const int d_lo = t >> 3;
            const size_t srow4 = (size_t)smax >> 2;
            const float4* src = kt + (size_t)bh * DHEAD * srow4;
            #pragma unroll
            for (int it = 0; it < 4; ++it) {
                int d = d_lo + it * 32;
                float4 v = src[(size_t)d * srow4 + (size_t)(s0 >> 2) + s4];
                tile[s4 * 4 + 0][d] = v.x;
                tile[s4 * 4 + 1][d] = v.y;
                tile[s4 * 4 + 2][d] = v.z;
                tile[s4 * 4 + 3][d] = v.w;
            }
            __syncthreads();
        }

        const int l = t & 31;
        const int w = t >> 5;
        float4* dst = out0 + (size_t)bh * smax * 32;
        #pragma unroll
        for (int it = 0; it < 4; ++it) {
            int s  = w + it * 8;
            int gs = s0 + s;
            int i  = g_inv[gs];
            float4 v;
            if (i > 0) v = k_val[((size_t)bh * snew + (size_t)(i - 1)) * 32 + l];
            else       v = *(const float4*)&tile[s][l * 4];
            dst[(size_t)gs * 32 + l] = v;
        }
    } else {
        size_t cb  = (size_t)(bid - q - 1);
        size_t idx = cb * 256 + t;
        size_t total = (size_t)BH * smax * 32;
        if (idx >= total) return;

        int j = (int)(idx & 31);
        size_t row = idx >> 5;
        int s = (int)(row % smax);
        size_t bh = row / smax;

        int i = g_inv[s];
        if (i > 0) {
            size_t src = ((bh * (size_t)snew) + (size_t)(i - 1)) * 32 + j;
            out1[idx] = k_val[src];
            out2[idx] = v_val[src];
        } else {
            out1[idx] = k_cache[idx];
            out2[idx] = v_cache[idx];
        }
    }
}

extern "C" void kernel_launch(void* const* d_in, const int* in_sizes, int n_in,
                              void* d_out, int out_size) {
    const int*   pos      = (const int*)d_in[0];
    const float* k_val    = (const float*)d_in[1];
    const float* v_val    = (const float*)d_in[2];
    const float* k_cache  = (const float*)d_in[3];
    const float* kt_cache = (const float*)d_in[4];
    const float* v_cache  = (const float*)d_in[5];

    int snew = in_sizes[0];
    int smax = in_sizes[3] / (BH * DHEAD);

    float* out  = (float*)d_out;
    size_t per  = (size_t)BH * smax * DHEAD;
    float* out0 = out;             // ktᵀ result
    float* out1 = out + per;       // k result
    float* out2 = out + 2 * per;   // v result

    int transBlocks = (smax / 32) * BH;           // 16384 for smax=8192
    int totalBlocks = transBlocks * 5;            // transpose + 4x copy

    if (smax == 8192 && snew == 512) {
        fused_all_kernel<8192, 512><<<totalBlocks, 256>>>(
            pos,
            (const float4*)kt_cache,
            (const float4*)k_cache, (const float4*)v_cache,
            (const float4*)k_val,   (const float4*)v_val,
            (float4*)out0, (float4*)out1, (float4*)out2);
    } else {
        scatter_inv_kernel<<<(snew + 511) / 512, 512>>>(pos, snew);
        fused_main_generic<<<totalBlocks, 256>>>(
            (const float4*)kt_cache,
            (const float4*)k_cache, (const float4*)v_cache,
            (const float4*)k_val,   (const float4*)v_val,
            (float4*)out0, (float4*)out1, (float4*)out2,
            smax, snew);
    }
}